// round 11
// baseline (speedup 1.0000x reference)
#include <cuda_runtime.h>

// LovaszSoftmax: B=8, C=21, H=W=512. Sort-free histogram formulation.
// R11: hierarchical survivor skip. pass1 publishes per-(class, 256-pixel-tile)
// max encoded bucket; pass2 assigns one warp per tile and skips the entire
// 512-byte tile read when its coarse max is below the class threshold
// (threshold = min foreground bucket; entries below it have identically-zero
// Lovasz gradient -> exact). ~90% of pass2's 88 MB scan is never read.

#define BATCH   8
#define NCLS    21
#define HW      (512*512)          // 262144 = 2^18
#define NPIX    (BATCH*HW)         // 2097152
#define KBINS   32768
#define NBINS   (NCLS*KBINS)
#define CHUNKS  8
#define KCH     (KBINS/CHUNKS)     // 4096
#define NTILES  (NPIX/256)         // 8192 coarse tiles (pass1 block granularity)

#define LOG2E_F 1.4426950408889634f
#define MAGICF  12582912.0f        // 1.5 * 2^23
#define SCALEF  32767.0f

// Scratch (allocation-free: __device__ globals)
__device__ unsigned long long g_hist[NBINS];        // (class,bin): count<<32 | fg
__device__ unsigned short g_buck[(size_t)NCLS * NPIX];  // 88 MB: v=(bkt<<1)|fg
__device__ unsigned short g_cmax[NCLS][NTILES];     // coarse per-tile max of v
__device__ unsigned g_minfg[NCLS];                  // v-encoded min fg bucket
__device__ unsigned g_partN[NCLS][CHUNKS];
__device__ unsigned g_partF[NCLS][CHUNKS];
__device__ float g_lossPart[NCLS][CHUNKS];
__device__ int g_label_shift;                       // 0: int32 labels, 1: int64

__global__ void zero_hist_kernel() {
    int i = blockIdx.x * blockDim.x + threadIdx.x;
    if (i < NBINS / 2) ((ulonglong2*)g_hist)[i] = make_ulonglong2(0ULL, 0ULL);
    if (i < NCLS) g_minfg[i] = 0xFFFFFFFFu;
}

// int32 vs int64 label layout detection (labels in [0,21): if int64, odd words
// are all-zero high halves; if int32 they are random labels).
__global__ void detect_labels_kernel(const unsigned* __restrict__ lw) {
    __shared__ int any_nonzero;
    if (threadIdx.x == 0) any_nonzero = 0;
    __syncthreads();
    int nz = 0;
    for (int i = threadIdx.x; i < 4096; i += blockDim.x)
        if (lw[2 * i + 1] != 0u) nz = 1;
    if (nz) atomicOr(&any_nonzero, 1);
    __syncthreads();
    if (threadIdx.x == 0) g_label_shift = any_nonzero ? 0 : 1;
}

__device__ __forceinline__ float frcp_fast(float z) {
    float r; asm("rcp.approx.f32 %0, %1;" : "=f"(r) : "f"(z)); return r;
}

// exp(v) via 2^(v*log2e): FMA/ALU pipes only (no MUFU). rel err ~1e-5.
__device__ __forceinline__ float exp_poly(float v) {
    float y = v * LOG2E_F;
    float t = y + MAGICF;
    int   n = __float_as_int(t) - 0x4B400000;
    float f = y - (t - MAGICF);
    float p = 0.0096181291f;
    p = fmaf(p, f, 0.0555041087f);
    p = fmaf(p, f, 0.2402265069f);
    p = fmaf(p, f, 0.6931471806f);
    p = fmaf(p, f, 1.0f);
    return __int_as_float(__float_as_int(p) + (n << 23));
}

// Pass 1: softmax -> store v=(bkt<<1)|fg; per-class min fg v; per-tile max v.
__global__ void __launch_bounds__(256) pass1_kernel(const float* __restrict__ x,
                                                    const unsigned* __restrict__ lw) {
    __shared__ unsigned sMin[NCLS];
    __shared__ unsigned sMax[NCLS];
    if (threadIdx.x < NCLS) { sMin[threadIdx.x] = 0xFFFFFFFFu; sMax[threadIdx.x] = 0u; }
    __syncthreads();

    int idx = blockIdx.x * 256 + threadIdx.x;    // pixel id
    int b = idx >> 18;
    long long base = (long long)b * (NCLS - 1) * HW + idx;  // == b*C*HW + hw

    float e[NCLS];
#pragma unroll
    for (int c = 0; c < NCLS; c++) e[c] = x[base + (long long)c * HW];

    float Z = 0.f;
#pragma unroll
    for (int c = 0; c < NCLS; c++) {
        e[c] = (c < 11) ? __expf(e[c]) : exp_poly(e[c]);   // split MUFU / FMA
        Z += e[c];
    }
    float is = SCALEF * frcp_fast(Z);

    int lab = (int)lw[(long long)idx << g_label_shift];
    int lane = threadIdx.x & 31;

    unsigned short* __restrict__ bp = &g_buck[idx];
    unsigned fgv = 0;
#pragma unroll
    for (int c = 0; c < NCLS; c++) {
        bool isfg = (lab == c);
        float fgs = isfg ? SCALEF : 0.0f;
        float err_s = fabsf(fmaf(e[c], -is, fgs));     // err * SCALE
        unsigned bkt = __float_as_uint(err_s + MAGICF) & 0x7FFFu;
        unsigned v = (bkt << 1) | (isfg ? 1u : 0u);
        bp[(size_t)c * NPIX] = (unsigned short)v;
        if (isfg) fgv = v;
        unsigned wmax = __reduce_max_sync(0xFFFFFFFFu, v);
        if (lane == 0) atomicMax(&sMax[c], wmax);
    }
    atomicMin(&sMin[lab], fgv);
    __syncthreads();
    if (threadIdx.x < NCLS) {
        if (sMin[threadIdx.x] != 0xFFFFFFFFu)
            atomicMin(&g_minfg[threadIdx.x], sMin[threadIdx.x]);
        g_cmax[threadIdx.x][blockIdx.x] = (unsigned short)sMax[threadIdx.x];
    }
}

// Pass 2: warp-per-tile; skip whole 512B tile when coarse max < threshold.
__global__ void __launch_bounds__(256) pass2_kernel() {
    const int c = blockIdx.y;
    unsigned mv = g_minfg[c];                    // (minbkt<<1)|1 or 0xFFFFFFFF
    unsigned thrv = (mv > 0xFFFFu) ? 0u : (mv & 0xFFFEu);

    int warp = threadIdx.x >> 5;
    int lane = threadIdx.x & 31;
    int tile = blockIdx.x * 8 + warp;

    unsigned cmax = g_cmax[c][tile];             // broadcast load
    if (cmax < thrv) return;                     // whole tile below threshold

    unsigned t2 = thrv | (thrv << 16);
    int t = tile * 32 + lane;                    // uint4 index (8 pixels)
    uint4 bv = ((const uint4*)(g_buck + (size_t)c * NPIX))[t];

    unsigned any = __vcmpgeu2(bv.x, t2) | __vcmpgeu2(bv.y, t2)
                 | __vcmpgeu2(bv.z, t2) | __vcmpgeu2(bv.w, t2);
    if (!any) return;

    unsigned long long* __restrict__ hc = &g_hist[c * KBINS];
    unsigned w[4] = {bv.x, bv.y, bv.z, bv.w};
#pragma unroll
    for (int j = 0; j < 8; j++) {
        unsigned v = (j & 1) ? (w[j >> 1] >> 16) : (w[j >> 1] & 0xFFFFu);
        if (v >= thrv)
            atomicAdd(&hc[v >> 1], 0x100000000ULL + (unsigned long long)(v & 1u));
    }
}

// Phase A: per-(class,chunk) totals of counts and fg counts.
__global__ void __launch_bounds__(1024) reduceA_kernel() {
    const int c = blockIdx.x >> 3;
    const int k = blockIdx.x & 7;
    const int tid = threadIdx.x;
    const int PER = KCH / 1024;    // 4

    __shared__ unsigned sN[1024], sF[1024];

    const unsigned long long* __restrict__ hist = &g_hist[c * KBINS + k * KCH];
    unsigned nSum = 0, fSum = 0;
#pragma unroll
    for (int j = 0; j < PER; j++) {
        unsigned long long h = hist[tid * PER + j];
        nSum += (unsigned)(h >> 32);
        fSum += (unsigned)(h & 0xFFFFFFFFu);
    }
    sN[tid] = nSum; sF[tid] = fSum;
    __syncthreads();
    for (int s = 512; s > 0; s >>= 1) {
        if (tid < s) { sN[tid] += sN[tid + s]; sF[tid] += sF[tid + s]; }
        __syncthreads();
    }
    if (tid == 0) { g_partN[c][k] = sN[0]; g_partF[c][k] = sF[0]; }
}

// Phase B: descending scan per (class,chunk), seeded with exact prefixes.
__global__ void __launch_bounds__(1024) reduceB_kernel() {
    const int c = blockIdx.x >> 3;
    const int k = blockIdx.x & 7;
    const int tid = threadIdx.x;
    const int PER = KCH / 1024;    // 4

    __shared__ unsigned snN[1024], snF[1024];
    __shared__ float sRed[1024];

    unsigned gtsN = 0, preN = 0, preF = 0;
#pragma unroll
    for (int kk = 0; kk < CHUNKS; kk++) {
        unsigned pn = g_partN[c][kk], pf = g_partF[c][kk];
        gtsN += pf;
        if (kk > k) { preN += pn; preF += pf; }
    }
    const float gts = (float)gtsN;

    const unsigned long long* __restrict__ hist = &g_hist[c * KBINS + k * KCH];

    unsigned nSum = 0, fSum = 0;
#pragma unroll
    for (int j = 0; j < PER; j++) {
        unsigned long long h = hist[KCH - 1 - (tid * PER + j)];
        nSum += (unsigned)(h >> 32);
        fSum += (unsigned)(h & 0xFFFFFFFFu);
    }
    snN[tid] = nSum; snF[tid] = fSum;
    __syncthreads();

    for (int off = 1; off < 1024; off <<= 1) {
        unsigned an = (tid >= off) ? snN[tid - off] : 0u;
        unsigned af = (tid >= off) ? snF[tid - off] : 0u;
        __syncthreads();
        snN[tid] += an; snF[tid] += af;
        __syncthreads();
    }

    const unsigned baseN = preN + snN[tid] - nSum;
    const unsigned baseF = preF + snF[tid] - fSum;

    unsigned cumN = baseN, cumF = baseF;
    float Jprev;
    if (baseN == 0) {
        Jprev = 0.f;
    } else {
        Jprev = 1.f - (gts - (float)baseF) / (gts + (float)(baseN - baseF));
    }
    float acc = 0.f;
#pragma unroll
    for (int j = 0; j < PER; j++) {
        int lbin = KCH - 1 - (tid * PER + j);
        unsigned long long h = hist[lbin];
        unsigned n = (unsigned)(h >> 32);
        unsigned f = (unsigned)(h & 0xFFFFFFFFu);
        if (n) {
            cumN += n; cumF += f;
            float J = 1.f - (gts - (float)cumF) / (gts + (float)(cumN - cumF));
            float eb = (float)(k * KCH + lbin) * (1.0f / SCALEF);
            acc += eb * (J - Jprev);
            Jprev = J;
        }
    }

    sRed[tid] = acc;
    __syncthreads();
    for (int s = 512; s > 0; s >>= 1) {
        if (tid < s) sRed[tid] += sRed[tid + s];
        __syncthreads();
    }
    if (tid == 0) g_lossPart[c][k] = sRed[0];
}

__global__ void final_kernel(float* __restrict__ out) {
    float s = 0.f;
    for (int c = 0; c < NCLS; c++) {
        float cl = 0.f;
        for (int k = 0; k < CHUNKS; k++) cl += g_lossPart[c][k];
        s += cl;
    }
    out[0] = s * (1.0f / (float)NCLS);   // LOSS_WEIGHT = 1
}

extern "C" void kernel_launch(void* const* d_in, const int* in_sizes, int n_in,
                              void* d_out, int out_size) {
    const float* x;
    const unsigned* labels;
    if (in_sizes[0] == NPIX * NCLS) {
        x = (const float*)d_in[0];
        labels = (const unsigned*)d_in[1];
    } else {
        x = (const float*)d_in[1];
        labels = (const unsigned*)d_in[0];
    }
    float* out = (float*)d_out;

    detect_labels_kernel<<<1, 256>>>(labels);
    zero_hist_kernel<<<(NBINS / 2 + 255) / 256, 256>>>();
    pass1_kernel<<<NPIX / 256, 256>>>(x, labels);
    {
        dim3 g(NTILES / 8, NCLS);
        pass2_kernel<<<g, 256>>>();
    }
    reduceA_kernel<<<NCLS * CHUNKS, 1024>>>();
    reduceB_kernel<<<NCLS * CHUNKS, 1024>>>();
    final_kernel<<<1, 1>>>(out);
}

// round 13
// speedup vs baseline: 1.2149x; 1.2149x over previous
#include <cuda_runtime.h>

// LovaszSoftmax: B=8, C=21, H=W=512. Sort-free histogram formulation.
// R12 = R10 skeleton (107us) with pass2 widened to 32 pixels/thread.
// pass2 is instruction-issue bound (R10: issue 51%, DRAM 25%); 4x uint4 per
// thread amortizes per-thread fixed cost over 4 loads. Buckets stored as
// v=(bkt<<1)|fg so pass2 needs no label reads; entries below the class's min
// foreground bucket have identically-zero Lovasz gradient and are dropped
// (exact — validated R8/R9/R10).

#define BATCH   8
#define NCLS    21
#define HW      (512*512)          // 262144 = 2^18
#define NPIX    (BATCH*HW)         // 2097152
#define KBINS   32768
#define NBINS   (NCLS*KBINS)
#define CHUNKS  8
#define KCH     (KBINS/CHUNKS)     // 4096

#define LOG2E_F 1.4426950408889634f
#define MAGICF  12582912.0f        // 1.5 * 2^23
#define SCALEF  32767.0f

// Scratch (allocation-free: __device__ globals)
__device__ unsigned long long g_hist[NBINS];        // (class,bin): count<<32 | fg
__device__ unsigned short g_buck[(size_t)NCLS * NPIX];  // 88 MB: v=(bkt<<1)|fg
__device__ unsigned g_minfg[NCLS];                  // v-encoded min fg bucket
__device__ unsigned g_partN[NCLS][CHUNKS];
__device__ unsigned g_partF[NCLS][CHUNKS];
__device__ float g_lossPart[NCLS][CHUNKS];
__device__ int g_label_shift;                       // 0: int32 labels, 1: int64

__global__ void zero_hist_kernel() {
    int i = blockIdx.x * blockDim.x + threadIdx.x;
    if (i < NBINS / 2) ((ulonglong2*)g_hist)[i] = make_ulonglong2(0ULL, 0ULL);
    if (i < NCLS) g_minfg[i] = 0xFFFFFFFFu;
}

// int32 vs int64 label layout detection (labels in [0,21): if int64, odd words
// are all-zero high halves; if int32 they are random labels).
__global__ void detect_labels_kernel(const unsigned* __restrict__ lw) {
    __shared__ int any_nonzero;
    if (threadIdx.x == 0) any_nonzero = 0;
    __syncthreads();
    int nz = 0;
    for (int i = threadIdx.x; i < 4096; i += blockDim.x)
        if (lw[2 * i + 1] != 0u) nz = 1;
    if (nz) atomicOr(&any_nonzero, 1);
    __syncthreads();
    if (threadIdx.x == 0) g_label_shift = any_nonzero ? 0 : 1;
}

__device__ __forceinline__ float frcp_fast(float z) {
    float r; asm("rcp.approx.f32 %0, %1;" : "=f"(r) : "f"(z)); return r;
}

// exp(v) via 2^(v*log2e): FMA/ALU pipes only (no MUFU). rel err ~1e-5.
__device__ __forceinline__ float exp_poly(float v) {
    float y = v * LOG2E_F;
    float t = y + MAGICF;
    int   n = __float_as_int(t) - 0x4B400000;
    float f = y - (t - MAGICF);
    float p = 0.0096181291f;
    p = fmaf(p, f, 0.0555041087f);
    p = fmaf(p, f, 0.2402265069f);
    p = fmaf(p, f, 0.6931471806f);
    p = fmaf(p, f, 1.0f);
    return __int_as_float(__float_as_int(p) + (n << 23));
}

// Pass 1: softmax -> store v=(bkt<<1)|fg per (class,pixel); per-class min fg v.
__global__ void __launch_bounds__(256) pass1_kernel(const float* __restrict__ x,
                                                    const unsigned* __restrict__ lw) {
    __shared__ unsigned sMin[NCLS];
    if (threadIdx.x < NCLS) sMin[threadIdx.x] = 0xFFFFFFFFu;
    __syncthreads();

    int idx = blockIdx.x * 256 + threadIdx.x;    // pixel id
    int b = idx >> 18;
    long long base = (long long)b * (NCLS - 1) * HW + idx;  // == b*C*HW + hw

    float e[NCLS];
#pragma unroll
    for (int c = 0; c < NCLS; c++) e[c] = x[base + (long long)c * HW];

    float Z = 0.f;
#pragma unroll
    for (int c = 0; c < NCLS; c++) {
        e[c] = (c < 11) ? __expf(e[c]) : exp_poly(e[c]);   // split MUFU / FMA
        Z += e[c];
    }
    float is = SCALEF * frcp_fast(Z);

    int lab = (int)lw[(long long)idx << g_label_shift];

    unsigned short* __restrict__ bp = &g_buck[idx];
    unsigned fgv = 0;
#pragma unroll
    for (int c = 0; c < NCLS; c++) {
        bool isfg = (lab == c);
        float fgs = isfg ? SCALEF : 0.0f;
        float err_s = fabsf(fmaf(e[c], -is, fgs));     // err * SCALE
        unsigned bkt = __float_as_uint(err_s + MAGICF) & 0x7FFFu;
        unsigned v = (bkt << 1) | (isfg ? 1u : 0u);
        bp[(size_t)c * NPIX] = (unsigned short)v;
        if (isfg) fgv = v;
    }
    atomicMin(&sMin[lab], fgv);
    __syncthreads();
    if (threadIdx.x < NCLS && sMin[threadIdx.x] != 0xFFFFFFFFu)
        atomicMin(&g_minfg[threadIdx.x], sMin[threadIdx.x]);
}

// Pass 2: label-free SIMD survivor scan, 32 pixels (4x uint4) per thread.
__global__ void __launch_bounds__(256) pass2_kernel() {
    const int c = blockIdx.y;
    unsigned mv = g_minfg[c];                    // (minbkt<<1)|1 or 0xFFFFFFFF
    unsigned thrv = (mv > 0xFFFFu) ? 0u : (mv & 0xFFFEu);
    unsigned t2 = thrv | (thrv << 16);

    const uint4* __restrict__ src = (const uint4*)(g_buck + (size_t)c * NPIX);
    unsigned long long* __restrict__ hc = &g_hist[c * KBINS];

    int base = blockIdx.x * 1024 + threadIdx.x;  // uint4 index, iter-coalesced

#pragma unroll
    for (int it = 0; it < 4; it++) {
        uint4 bv = src[base + it * 256];
        unsigned any = __vcmpgeu2(bv.x, t2) | __vcmpgeu2(bv.y, t2)
                     | __vcmpgeu2(bv.z, t2) | __vcmpgeu2(bv.w, t2);
        if (!any) continue;                      // no survivors in these 8 px

        unsigned w[4] = {bv.x, bv.y, bv.z, bv.w};
#pragma unroll
        for (int j = 0; j < 8; j++) {
            unsigned v = (j & 1) ? (w[j >> 1] >> 16) : (w[j >> 1] & 0xFFFFu);
            if (v >= thrv)
                atomicAdd(&hc[v >> 1],
                          0x100000000ULL + (unsigned long long)(v & 1u));
        }
    }
}

// Phase A: per-(class,chunk) totals of counts and fg counts.
__global__ void __launch_bounds__(1024) reduceA_kernel() {
    const int c = blockIdx.x >> 3;
    const int k = blockIdx.x & 7;
    const int tid = threadIdx.x;
    const int PER = KCH / 1024;    // 4

    __shared__ unsigned sN[1024], sF[1024];

    const unsigned long long* __restrict__ hist = &g_hist[c * KBINS + k * KCH];
    unsigned nSum = 0, fSum = 0;
#pragma unroll
    for (int j = 0; j < PER; j++) {
        unsigned long long h = hist[tid * PER + j];
        nSum += (unsigned)(h >> 32);
        fSum += (unsigned)(h & 0xFFFFFFFFu);
    }
    sN[tid] = nSum; sF[tid] = fSum;
    __syncthreads();
    for (int s = 512; s > 0; s >>= 1) {
        if (tid < s) { sN[tid] += sN[tid + s]; sF[tid] += sF[tid + s]; }
        __syncthreads();
    }
    if (tid == 0) { g_partN[c][k] = sN[0]; g_partF[c][k] = sF[0]; }
}

// Phase B: descending scan per (class,chunk), seeded with exact prefixes.
__global__ void __launch_bounds__(1024) reduceB_kernel() {
    const int c = blockIdx.x >> 3;
    const int k = blockIdx.x & 7;
    const int tid = threadIdx.x;
    const int PER = KCH / 1024;    // 4

    __shared__ unsigned snN[1024], snF[1024];
    __shared__ float sRed[1024];

    unsigned gtsN = 0, preN = 0, preF = 0;
#pragma unroll
    for (int kk = 0; kk < CHUNKS; kk++) {
        unsigned pn = g_partN[c][kk], pf = g_partF[c][kk];
        gtsN += pf;
        if (kk > k) { preN += pn; preF += pf; }
    }
    const float gts = (float)gtsN;

    const unsigned long long* __restrict__ hist = &g_hist[c * KBINS + k * KCH];

    unsigned nSum = 0, fSum = 0;
#pragma unroll
    for (int j = 0; j < PER; j++) {
        unsigned long long h = hist[KCH - 1 - (tid * PER + j)];
        nSum += (unsigned)(h >> 32);
        fSum += (unsigned)(h & 0xFFFFFFFFu);
    }
    snN[tid] = nSum; snF[tid] = fSum;
    __syncthreads();

    for (int off = 1; off < 1024; off <<= 1) {
        unsigned an = (tid >= off) ? snN[tid - off] : 0u;
        unsigned af = (tid >= off) ? snF[tid - off] : 0u;
        __syncthreads();
        snN[tid] += an; snF[tid] += af;
        __syncthreads();
    }

    const unsigned baseN = preN + snN[tid] - nSum;
    const unsigned baseF = preF + snF[tid] - fSum;

    unsigned cumN = baseN, cumF = baseF;
    float Jprev;
    if (baseN == 0) {
        Jprev = 0.f;
    } else {
        Jprev = 1.f - (gts - (float)baseF) / (gts + (float)(baseN - baseF));
    }
    float acc = 0.f;
#pragma unroll
    for (int j = 0; j < PER; j++) {
        int lbin = KCH - 1 - (tid * PER + j);
        unsigned long long h = hist[lbin];
        unsigned n = (unsigned)(h >> 32);
        unsigned f = (unsigned)(h & 0xFFFFFFFFu);
        if (n) {
            cumN += n; cumF += f;
            float J = 1.f - (gts - (float)cumF) / (gts + (float)(cumN - cumF));
            float eb = (float)(k * KCH + lbin) * (1.0f / SCALEF);
            acc += eb * (J - Jprev);
            Jprev = J;
        }
    }

    sRed[tid] = acc;
    __syncthreads();
    for (int s = 512; s > 0; s >>= 1) {
        if (tid < s) sRed[tid] += sRed[tid + s];
        __syncthreads();
    }
    if (tid == 0) g_lossPart[c][k] = sRed[0];
}

__global__ void final_kernel(float* __restrict__ out) {
    float s = 0.f;
    for (int c = 0; c < NCLS; c++) {
        float cl = 0.f;
        for (int k = 0; k < CHUNKS; k++) cl += g_lossPart[c][k];
        s += cl;
    }
    out[0] = s * (1.0f / (float)NCLS);   // LOSS_WEIGHT = 1
}

extern "C" void kernel_launch(void* const* d_in, const int* in_sizes, int n_in,
                              void* d_out, int out_size) {
    const float* x;
    const unsigned* labels;
    if (in_sizes[0] == NPIX * NCLS) {
        x = (const float*)d_in[0];
        labels = (const unsigned*)d_in[1];
    } else {
        x = (const float*)d_in[1];
        labels = (const unsigned*)d_in[0];
    }
    float* out = (float*)d_out;

    detect_labels_kernel<<<1, 256>>>(labels);
    zero_hist_kernel<<<(NBINS / 2 + 255) / 256, 256>>>();
    pass1_kernel<<<NPIX / 256, 256>>>(x, labels);
    {
        dim3 g(NPIX / 2 / 1024 / 4, NCLS);   // uint4 = 8 px; 4 per thread; 256 thr
        pass2_kernel<<<g, 256>>>();
    }
    reduceA_kernel<<<NCLS * CHUNKS, 1024>>>();
    reduceB_kernel<<<NCLS * CHUNKS, 1024>>>();
    final_kernel<<<1, 1>>>(out);
}